// round 4
// baseline (speedup 1.0000x reference)
#include <cuda_runtime.h>
#include <math.h>

#define T_STEPS 32
#define NB 20000
#define FD 128
#define HD 128
#define CD 10
#define MR 144
#define LN_EPS 1e-5f

// Scratch (static __device__ — allocation-free per harness rules)
__device__ float g_Z[(size_t)T_STEPS * NB * HD];   // 327.7 MB: Z = X@W_ih^T + b_ih + b_hh
__device__ float g_L[(size_t)T_STEPS * NB];        // attn logits
__device__ float g_D[(size_t)T_STEPS * NB * CD];   // dense outputs per step

// ---------------------------------------------------------------------------
// Kernel 1: Z[t,n,j] = sum_k X[t,n,k] * W_ih[j,k] + b_ih[j] + b_hh[j]
// GEMM: 640000 x 128 (K=128). Tile 128x128, 256 thr, 8x8 micro-tile.
// Double-buffered K-chunks of X (one barrier per chunk).
// ---------------------------------------------------------------------------
extern "C" __global__ void __launch_bounds__(256, 2)
k1_zgemm(const float* __restrict__ X, const float* __restrict__ W_ih,
         const float* __restrict__ b_ih, const float* __restrict__ b_hh)
{
    extern __shared__ float sm1[];
    float* Wt  = sm1;                      // [128][128]  Wt[k][j] = W_ih[j][k]
    float* Xs0 = sm1 + HD * FD;            // [128][32]   K-chunk buffers (double)
    float* Xs1 = Xs0 + 128 * 32;

    const int tid = threadIdx.x;
    for (int idx = tid; idx < HD * FD; idx += 256) {
        int j = idx >> 7, k = idx & 127;
        Wt[k * HD + j] = W_ih[idx];
    }

    const int row0 = blockIdx.x * 128;
    const int ty = tid >> 4, tx = tid & 15;
    const int r0 = ty * 8, c0 = tx * 8;

    // coalesced float4 loader for one 128x32 K-chunk
    const int lr = tid >> 3, lc = tid & 7;   // row 0..31 step, col-group 0..7
    auto load_chunk = [&](float* dst, int kb) {
        #pragma unroll
        for (int q = 0; q < 4; q++) {
            int r = lr + q * 32;
            float4 v = *reinterpret_cast<const float4*>(
                X + (size_t)(row0 + r) * FD + kb * 32 + lc * 4);
            *reinterpret_cast<float4*>(dst + r * 32 + lc * 4) = v;
        }
    };

    float acc[8][8];
    {
        float bias[8];
        #pragma unroll
        for (int c = 0; c < 8; c++) bias[c] = b_ih[c0 + c] + b_hh[c0 + c];
        #pragma unroll
        for (int i = 0; i < 8; i++)
            #pragma unroll
            for (int c = 0; c < 8; c++) acc[i][c] = bias[c];
    }

    load_chunk(Xs0, 0);
    __syncthreads();            // Wt + first chunk ready

    #pragma unroll 1
    for (int kb = 0; kb < 4; ++kb) {
        float* cur = (kb & 1) ? Xs1 : Xs0;
        float* nxt = (kb & 1) ? Xs0 : Xs1;
        if (kb < 3) load_chunk(nxt, kb + 1);   // overlaps with compute below

        #pragma unroll 4
        for (int k = 0; k < 32; k += 2) {
            float2 a2[8];
            #pragma unroll
            for (int i = 0; i < 8; i++)
                a2[i] = *reinterpret_cast<const float2*>(cur + (r0 + i) * 32 + k);
            #pragma unroll
            for (int kk = 0; kk < 2; kk++) {
                const float* wr = Wt + (kb * 32 + k + kk) * HD + c0;
                float4 b0 = *reinterpret_cast<const float4*>(wr);
                float4 b1 = *reinterpret_cast<const float4*>(wr + 4);
                float bb[8] = {b0.x, b0.y, b0.z, b0.w, b1.x, b1.y, b1.z, b1.w};
                #pragma unroll
                for (int i = 0; i < 8; i++) {
                    float av = kk ? a2[i].y : a2[i].x;
                    #pragma unroll
                    for (int c = 0; c < 8; c++)
                        acc[i][c] = fmaf(av, bb[c], acc[i][c]);
                }
            }
        }
        __syncthreads();        // next chunk loaded AND cur fully consumed
    }

    #pragma unroll
    for (int i = 0; i < 8; i++) {
        float* zr = g_Z + (size_t)(row0 + r0 + i) * HD + c0;
        *reinterpret_cast<float4*>(zr) =
            make_float4(acc[i][0], acc[i][1], acc[i][2], acc[i][3]);
        *reinterpret_cast<float4*>(zr + 4) =
            make_float4(acc[i][4], acc[i][5], acc[i][6], acc[i][7]);
    }
}

// ---------------------------------------------------------------------------
// 16-lane (tx dimension) butterfly allreduce; both warp halves independent.
// ---------------------------------------------------------------------------
__device__ __forceinline__ float red16(float v)
{
    v += __shfl_xor_sync(0xffffffffu, v, 1);
    v += __shfl_xor_sync(0xffffffffu, v, 2);
    v += __shfl_xor_sync(0xffffffffu, v, 4);
    v += __shfl_xor_sync(0xffffffffu, v, 8);
    return v;
}

// ---------------------------------------------------------------------------
// Kernel 2: persistent recurrence. 139 CTAs x 144 rows (single wave, 148 SMs).
// Per step: acc = Z[t]; acc += h @ W_hh^T (SMEM); relu -> new h;
// LayerNorm + attn logit + dense(10) via shfl reductions -> g_L / g_D.
// ---------------------------------------------------------------------------
extern "C" __global__ void __launch_bounds__(288, 1)
k2_recur(const float* __restrict__ W_hh,
         const float* __restrict__ ln_gamma, const float* __restrict__ ln_beta,
         const float* __restrict__ attn_W,   const float* __restrict__ attn_b,
         const float* __restrict__ dense_W,  const float* __restrict__ dense_b)
{
    extern __shared__ float sm2[];
    float* Wt = sm2;                 // [128][128]  Wt[k][j] = W_hh[j][k]
    float* hs = sm2 + HD * HD;       // [144][128]  hidden state tile
    float* dW = hs + MR * HD;        // [10][128]

    const int tid = threadIdx.x;
    for (int idx = tid; idx < HD * HD; idx += 288) {
        int j = idx >> 7, k = idx & 127;
        Wt[k * HD + j] = W_hh[idx];
    }
    for (int idx = tid; idx < CD * HD; idx += 288) dW[idx] = dense_W[idx];

    const int row0 = blockIdx.x * MR;
    const int ty = tid / 16, tx = tid % 16;   // ty 0..17, tx 0..15
    const int r0 = ty * 8, c0 = tx * 8;

    float gam[8], bet[8], aw[8], db[CD];
    #pragma unroll
    for (int c = 0; c < 8; c++) {
        gam[c] = ln_gamma[c0 + c];
        bet[c] = ln_beta[c0 + c];
        aw[c]  = attn_W[c0 + c];
    }
    #pragma unroll
    for (int c = 0; c < CD; c++) db[c] = dense_b[c];
    const float ab = attn_b[0];

    // h0 = Z[0]  (reference init branch: no ReLU)
    for (int idx = tid; idx < MR * HD; idx += 288) {
        int r = idx >> 7, j = idx & 127;
        int gr = row0 + r;
        hs[idx] = (gr < NB) ? g_Z[(size_t)gr * HD + j] : 0.f;
    }
    __syncthreads();

    for (int t = 0; t < T_STEPS; t++) {
        // --- accumulator init = Z[t] tile (folds global load + bias add) ---
        float acc[8][8];
        const float* Zt = g_Z + (size_t)t * NB * HD;
        #pragma unroll
        for (int i = 0; i < 8; i++) {
            int gr = row0 + r0 + i;
            if (gr < NB) {
                float4 z0 = *reinterpret_cast<const float4*>(Zt + (size_t)gr * HD + c0);
                float4 z1 = *reinterpret_cast<const float4*>(Zt + (size_t)gr * HD + c0 + 4);
                acc[i][0] = z0.x; acc[i][1] = z0.y; acc[i][2] = z0.z; acc[i][3] = z0.w;
                acc[i][4] = z1.x; acc[i][5] = z1.y; acc[i][6] = z1.z; acc[i][7] = z1.w;
            } else {
                #pragma unroll
                for (int c = 0; c < 8; c++) acc[i][c] = 0.f;
            }
        }

        // --- GEMM: acc += hs @ Wt, K = 128 ---
        #pragma unroll 2
        for (int k = 0; k < HD; k += 4) {
            float4 a4[8];
            #pragma unroll
            for (int i = 0; i < 8; i++)
                a4[i] = *reinterpret_cast<const float4*>(hs + (r0 + i) * HD + k);
            #pragma unroll
            for (int kk = 0; kk < 4; kk++) {
                const float* wr = Wt + (k + kk) * HD + c0;
                float4 b0 = *reinterpret_cast<const float4*>(wr);
                float4 b1 = *reinterpret_cast<const float4*>(wr + 4);
                float bb[8] = {b0.x, b0.y, b0.z, b0.w, b1.x, b1.y, b1.z, b1.w};
                #pragma unroll
                for (int i = 0; i < 8; i++) {
                    float av = (kk == 0) ? a4[i].x : (kk == 1) ? a4[i].y
                             : (kk == 2) ? a4[i].z : a4[i].w;
                    #pragma unroll
                    for (int c = 0; c < 8; c++)
                        acc[i][c] = fmaf(av, bb[c], acc[i][c]);
                }
            }
        }

        // --- ReLU: this IS the new recurrent state (pre-LayerNorm) ---
        #pragma unroll
        for (int i = 0; i < 8; i++)
            #pragma unroll
            for (int c = 0; c < 8; c++) acc[i][c] = fmaxf(acc[i][c], 0.f);

        __syncthreads();   // all GEMM reads of hs complete
        #pragma unroll
        for (int i = 0; i < 8; i++) {
            float* hr = hs + (r0 + i) * HD + c0;
            *reinterpret_cast<float4*>(hr) =
                make_float4(acc[i][0], acc[i][1], acc[i][2], acc[i][3]);
            *reinterpret_cast<float4*>(hr + 4) =
                make_float4(acc[i][4], acc[i][5], acc[i][6], acc[i][7]);
        }

        // --- LayerNorm (population var) in-place on acc ---
        float mu[8], rs[8];
        #pragma unroll
        for (int i = 0; i < 8; i++) {
            float s = 0.f, q = 0.f;
            #pragma unroll
            for (int c = 0; c < 8; c++) { s += acc[i][c]; q += acc[i][c] * acc[i][c]; }
            s = red16(s);
            q = red16(q);
            float m = s * (1.f / 128.f);
            float v = q * (1.f / 128.f) - m * m;
            mu[i] = m;
            rs[i] = rsqrtf(v + LN_EPS);
        }
        #pragma unroll
        for (int i = 0; i < 8; i++)
            #pragma unroll
            for (int c = 0; c < 8; c++)
                acc[i][c] = (acc[i][c] - mu[i]) * rs[i] * gam[c] + bet[c];

        // --- attention logit ---
        float lg[8];
        #pragma unroll
        for (int i = 0; i < 8; i++) {
            float s = 0.f;
            #pragma unroll
            for (int c = 0; c < 8; c++) s = fmaf(acc[i][c], aw[c], s);
            lg[i] = red16(s);
        }
        if (tx == 0) {
            #pragma unroll
            for (int i = 0; i < 8; i++) {
                int gr = row0 + r0 + i;
                if (gr < NB) g_L[(size_t)t * NB + gr] = lg[i] + ab;
            }
        }

        // --- dense head (10 classes) ---
        #pragma unroll
        for (int cls = 0; cls < CD; cls++) {
            const float* wr = dW + cls * HD + c0;
            float4 w0 = *reinterpret_cast<const float4*>(wr);
            float4 w1 = *reinterpret_cast<const float4*>(wr + 4);
            float wb[8] = {w0.x, w0.y, w0.z, w0.w, w1.x, w1.y, w1.z, w1.w};
            #pragma unroll
            for (int i = 0; i < 8; i++) {
                float s = 0.f;
                #pragma unroll
                for (int c = 0; c < 8; c++) s = fmaf(acc[i][c], wb[c], s);
                s = red16(s);
                if (tx == 0) {
                    int gr = row0 + r0 + i;
                    if (gr < NB)
                        g_D[((size_t)t * NB + gr) * CD + cls] = s + db[cls];
                }
            }
        }

        __syncthreads();   // hs writes visible before next GEMM
    }
}

// ---------------------------------------------------------------------------
// Kernel 3: softmax over T + attention-weighted sum -> out (N, 10)
// ---------------------------------------------------------------------------
extern "C" __global__ void k3_attn(float* __restrict__ out)
{
    int n = blockIdx.x * 256 + threadIdx.x;
    if (n >= NB) return;

    float lw[T_STEPS];
    float m = -1e30f;
    #pragma unroll
    for (int t = 0; t < T_STEPS; t++) {
        lw[t] = g_L[(size_t)t * NB + n];
        m = fmaxf(m, lw[t]);
    }
    float s = 0.f;
    #pragma unroll
    for (int t = 0; t < T_STEPS; t++) {
        lw[t] = expf(lw[t] - m);
        s += lw[t];
    }
    float inv = 1.f / s;

    float acc[CD];
    #pragma unroll
    for (int c = 0; c < CD; c++) acc[c] = 0.f;
    for (int t = 0; t < T_STEPS; t++) {
        float w = lw[t] * inv;
        const float* dp = g_D + ((size_t)t * NB + n) * CD;
        #pragma unroll
        for (int c = 0; c < CD; c++) acc[c] = fmaf(w, dp[c], acc[c]);
    }
    #pragma unroll
    for (int c = 0; c < CD; c++) out[n * CD + c] = acc[c];
}

// ---------------------------------------------------------------------------
extern "C" void kernel_launch(void* const* d_in, const int* in_sizes, int n_in,
                              void* d_out, int out_size)
{
    const float* X       = (const float*)d_in[0];
    const float* W_ih    = (const float*)d_in[1];
    const float* W_hh    = (const float*)d_in[2];
    const float* b_ih    = (const float*)d_in[3];
    const float* b_hh    = (const float*)d_in[4];
    const float* ln_g    = (const float*)d_in[5];
    const float* ln_b    = (const float*)d_in[6];
    const float* attn_W  = (const float*)d_in[7];
    const float* attn_b  = (const float*)d_in[8];
    const float* dense_W = (const float*)d_in[9];
    const float* dense_b = (const float*)d_in[10];
    (void)in_sizes; (void)n_in; (void)out_size;

    const int smem1 = (HD * FD + 2 * 128 * 32) * (int)sizeof(float);      // 96 KB
    const int smem2 = (HD * HD + MR * HD + CD * HD) * (int)sizeof(float); // 141 KB
    cudaFuncSetAttribute(k1_zgemm, cudaFuncAttributeMaxDynamicSharedMemorySize, smem1);
    cudaFuncSetAttribute(k2_recur, cudaFuncAttributeMaxDynamicSharedMemorySize, smem2);

    k1_zgemm<<<(T_STEPS * NB) / 128, 256, smem1>>>(X, W_ih, b_ih, b_hh);
    k2_recur<<<(NB + MR - 1) / MR, 288, smem2>>>(W_hh, ln_g, ln_b,
                                                 attn_W, attn_b, dense_W, dense_b);
    k3_attn<<<(NB + 255) / 256, 256>>>((float*)d_out);
}

// round 7
// speedup vs baseline: 1.3963x; 1.3963x over previous
#include <cuda_runtime.h>
#include <math.h>
#include <stdint.h>

#define T_STEPS 32
#define NB 20000
#define FD 128
#define HD 128
#define CD 10
#define LN_EPS 1e-5f

#define MR 160            // k2 rows per CTA: 125 CTAs exactly, single wave
#define K2_THREADS 320    // 10 warps: 5 m x 2 n (32x64 warp tiles)
#define K1_ROWS 256
#define K1_THREADS 512    // 16 warps: 8 m x 2 n

#define WS2 132           // W smem row stride in float2: >=128 cap, conflict-free B loads
#define HSS 132           // hs row stride (floats): 132%32==4 -> conflict-free A loads
#define XSS 36            // X chunk row stride (floats): 36%32==4

// Scratch (static __device__ — allocation-free per harness rules)
__device__ float g_Z[(size_t)T_STEPS * NB * HD];
__device__ float g_L[(size_t)T_STEPS * NB];
__device__ float g_D[(size_t)T_STEPS * NB * CD];

__device__ __forceinline__ uint32_t f2tf32(float x) {
    uint32_t r;
    asm("cvt.rna.tf32.f32 %0, %1;" : "=r"(r) : "f"(x));
    return r;
}

// D += A * B, m16n8k8 tf32, acc in-place
__device__ __forceinline__ void mma8(float* c, const uint32_t* a, uint32_t b0, uint32_t b1) {
    asm volatile(
        "mma.sync.aligned.m16n8k8.row.col.f32.tf32.tf32.f32 "
        "{%0,%1,%2,%3}, {%4,%5,%6,%7}, {%8,%9}, {%0,%1,%2,%3};"
        : "+f"(c[0]), "+f"(c[1]), "+f"(c[2]), "+f"(c[3])
        : "r"(a[0]), "r"(a[1]), "r"(a[2]), "r"(a[3]), "r"(b0), "r"(b1));
}

// split fp32 -> (tf32 hi, tf32 lo) register pair
__device__ __forceinline__ void split_tf32(float x, uint32_t& hi, uint32_t& lo) {
    hi = f2tf32(x);
    lo = f2tf32(x - __uint_as_float(hi));
}

// ---------------------------------------------------------------------------
// Kernel 1: Z = X @ W_ih^T + (b_ih + b_hh), tensor cores (3xTF32).
// 2500 CTAs x 256 rows, 512 thr (16 warps: 8m x 2n of 32x64 tiles).
// X K-chunks (256x32) double-buffered.
// ---------------------------------------------------------------------------
extern "C" __global__ void __launch_bounds__(K1_THREADS, 1)
k1_zgemm(const float* __restrict__ X, const float* __restrict__ W_ih,
         const float* __restrict__ b_ih, const float* __restrict__ b_hh)
{
    extern __shared__ float smraw[];
    float2* Wp  = (float2*)smraw;               // [128][WS2] (hi, lo) of W_ih^T
    float*  Xs0 = smraw + 2 * 128 * WS2;        // [256][XSS]
    float*  Xs1 = Xs0 + K1_ROWS * XSS;

    const int tid = threadIdx.x;
    // presplit W: Wp[k][j] = split(W_ih[j][k])
    for (int idx = tid; idx < HD * FD; idx += K1_THREADS) {
        int j = idx >> 7, k = idx & 127;
        float w = W_ih[idx];
        uint32_t hb, lb;
        split_tf32(w, hb, lb);
        Wp[k * WS2 + j] = make_float2(__uint_as_float(hb), __uint_as_float(lb));
    }

    const int row0 = blockIdx.x * K1_ROWS;
    const int wid  = tid >> 5, lane = tid & 31;
    const int g = lane >> 2, q = lane & 3;
    const int m0 = (wid & 7) * 32, n0 = (wid >> 3) * 64;

    const int lr = tid >> 3, lc = tid & 7;   // 64 row-steps x 8 col-groups
    auto load_chunk = [&](float* dst, int kb) {
        #pragma unroll
        for (int p = 0; p < 4; p++) {
            int r = lr + p * 64;
            float4 v = *reinterpret_cast<const float4*>(
                X + (size_t)(row0 + r) * FD + kb * 32 + lc * 4);
            *reinterpret_cast<float4*>(dst + r * XSS + lc * 4) = v;
        }
    };

    // acc init = bias broadcast
    float acc[2][8][4];
    #pragma unroll
    for (int nt = 0; nt < 8; nt++) {
        int j = n0 + nt * 8 + 2 * q;
        float bx = b_ih[j] + b_hh[j];
        float by = b_ih[j + 1] + b_hh[j + 1];
        #pragma unroll
        for (int mt = 0; mt < 2; mt++) {
            acc[mt][nt][0] = bx; acc[mt][nt][1] = by;
            acc[mt][nt][2] = bx; acc[mt][nt][3] = by;
        }
    }

    load_chunk(Xs0, 0);
    __syncthreads();

    #pragma unroll 1
    for (int kb = 0; kb < 4; kb++) {
        float* cur = (kb & 1) ? Xs1 : Xs0;
        float* nxt = (kb & 1) ? Xs0 : Xs1;
        if (kb < 3) load_chunk(nxt, kb + 1);

        #pragma unroll
        for (int k0 = 0; k0 < 32; k0 += 8) {
            uint32_t ahi[2][4], alo[2][4];
            #pragma unroll
            for (int mt = 0; mt < 2; mt++) {
                int rb = m0 + mt * 16 + g;
                split_tf32(cur[rb * XSS + k0 + q],           ahi[mt][0], alo[mt][0]);
                split_tf32(cur[(rb + 8) * XSS + k0 + q],     ahi[mt][1], alo[mt][1]);
                split_tf32(cur[rb * XSS + k0 + q + 4],       ahi[mt][2], alo[mt][2]);
                split_tf32(cur[(rb + 8) * XSS + k0 + q + 4], ahi[mt][3], alo[mt][3]);
            }
            #pragma unroll
            for (int nt = 0; nt < 8; nt++) {
                float2 w0 = Wp[(kb * 32 + k0 + q) * WS2 + n0 + nt * 8 + g];
                float2 w1 = Wp[(kb * 32 + k0 + q + 4) * WS2 + n0 + nt * 8 + g];
                uint32_t bh0 = __float_as_uint(w0.x), bh1 = __float_as_uint(w1.x);
                uint32_t bl0 = __float_as_uint(w0.y), bl1 = __float_as_uint(w1.y);
                #pragma unroll
                for (int mt = 0; mt < 2; mt++) {
                    mma8(acc[mt][nt], ahi[mt], bh0, bh1);
                    mma8(acc[mt][nt], alo[mt], bh0, bh1);
                    mma8(acc[mt][nt], ahi[mt], bl0, bl1);
                }
            }
        }
        __syncthreads();
    }

    // store Z (fragment layout -> row-major, float2 per half)
    #pragma unroll
    for (int mt = 0; mt < 2; mt++) {
        int r = row0 + m0 + mt * 16 + g;
        #pragma unroll
        for (int nt = 0; nt < 8; nt++) {
            int j = n0 + nt * 8 + 2 * q;
            *(float2*)&g_Z[(size_t)r * HD + j] =
                make_float2(acc[mt][nt][0], acc[mt][nt][1]);
            *(float2*)&g_Z[(size_t)(r + 8) * HD + j] =
                make_float2(acc[mt][nt][2], acc[mt][nt][3]);
        }
    }
}

// ---------------------------------------------------------------------------
__device__ __forceinline__ float red16(float v)
{
    v += __shfl_xor_sync(0xffffffffu, v, 1);
    v += __shfl_xor_sync(0xffffffffu, v, 2);
    v += __shfl_xor_sync(0xffffffffu, v, 4);
    v += __shfl_xor_sync(0xffffffffu, v, 8);
    return v;
}

// ---------------------------------------------------------------------------
// Kernel 2: recurrence, tensor cores. 125 CTAs x 160 rows (exact, one wave).
// Per step: acc = Z[t]; acc += h @ W_hh^T (3xTF32); relu -> hs;
// scalar epilogue (LN + attn + dense) from SMEM.
// ---------------------------------------------------------------------------
extern "C" __global__ void __launch_bounds__(K2_THREADS, 1)
k2_recur(const float* __restrict__ W_hh,
         const float* __restrict__ ln_gamma, const float* __restrict__ ln_beta,
         const float* __restrict__ attn_W,   const float* __restrict__ attn_b,
         const float* __restrict__ dense_W,  const float* __restrict__ dense_b)
{
    extern __shared__ float smraw[];
    float2* Wp  = (float2*)smraw;               // [128][WS2] (hi, lo) of W_hh^T
    float*  hs  = smraw + 2 * 128 * WS2;        // [160][HSS]
    float*  dWs = hs + MR * HSS;                // [10][128]

    const int tid = threadIdx.x;
    for (int idx = tid; idx < HD * HD; idx += K2_THREADS) {
        int j = idx >> 7, k = idx & 127;
        float w = W_hh[idx];
        uint32_t hb, lb;
        split_tf32(w, hb, lb);
        Wp[k * WS2 + j] = make_float2(__uint_as_float(hb), __uint_as_float(lb));
    }
    for (int idx = tid; idx < CD * HD; idx += K2_THREADS) dWs[idx] = dense_W[idx];

    const int row0 = blockIdx.x * MR;
    const int wid  = tid >> 5, lane = tid & 31;
    const int g = lane >> 2, q = lane & 3;
    const int m0 = (wid >> 1) * 32, n0 = (wid & 1) * 64;

    // scalar-epilogue mapping: 20 ty x 16 tx, 8 rows x 8 cols per thread
    const int ty = tid / 16, tx = tid % 16;
    const int er0 = ty * 8, ec0 = tx * 8;

    float gam[8], bet[8], aw[8], db[CD];
    #pragma unroll
    for (int c = 0; c < 8; c++) {
        gam[c] = ln_gamma[ec0 + c];
        bet[c] = ln_beta[ec0 + c];
        aw[c]  = attn_W[ec0 + c];
    }
    #pragma unroll
    for (int c = 0; c < CD; c++) db[c] = dense_b[c];
    const float ab = attn_b[0];

    // h0 = Z[0] (reference init branch: no ReLU)
    for (int f = tid; f < MR * 32; f += K2_THREADS) {
        int r = f >> 5, c4 = (f & 31) * 4;
        float4 v = *(const float4*)&g_Z[(size_t)(row0 + r) * HD + c4];
        *(float4*)&hs[r * HSS + c4] = v;
    }
    __syncthreads();

    #pragma unroll 1
    for (int t = 0; t < T_STEPS; t++) {
        const float* Zt = g_Z + ((size_t)t * NB + row0) * HD;

        // acc init = Z[t] in fragment layout
        float acc[2][8][4];
        #pragma unroll
        for (int mt = 0; mt < 2; mt++) {
            int rb = m0 + mt * 16 + g;
            #pragma unroll
            for (int nt = 0; nt < 8; nt++) {
                int j = n0 + nt * 8 + 2 * q;
                float2 z0 = *(const float2*)&Zt[(size_t)rb * HD + j];
                float2 z1 = *(const float2*)&Zt[(size_t)(rb + 8) * HD + j];
                acc[mt][nt][0] = z0.x; acc[mt][nt][1] = z0.y;
                acc[mt][nt][2] = z1.x; acc[mt][nt][3] = z1.y;
            }
        }

        // acc += h @ W_hh^T (3xTF32)
        #pragma unroll 2
        for (int k0 = 0; k0 < HD; k0 += 8) {
            uint32_t ahi[2][4], alo[2][4];
            #pragma unroll
            for (int mt = 0; mt < 2; mt++) {
                int rb = m0 + mt * 16 + g;
                split_tf32(hs[rb * HSS + k0 + q],           ahi[mt][0], alo[mt][0]);
                split_tf32(hs[(rb + 8) * HSS + k0 + q],     ahi[mt][1], alo[mt][1]);
                split_tf32(hs[rb * HSS + k0 + q + 4],       ahi[mt][2], alo[mt][2]);
                split_tf32(hs[(rb + 8) * HSS + k0 + q + 4], ahi[mt][3], alo[mt][3]);
            }
            #pragma unroll
            for (int nt = 0; nt < 8; nt++) {
                float2 w0 = Wp[(k0 + q) * WS2 + n0 + nt * 8 + g];
                float2 w1 = Wp[(k0 + q + 4) * WS2 + n0 + nt * 8 + g];
                uint32_t bh0 = __float_as_uint(w0.x), bh1 = __float_as_uint(w1.x);
                uint32_t bl0 = __float_as_uint(w0.y), bl1 = __float_as_uint(w1.y);
                #pragma unroll
                for (int mt = 0; mt < 2; mt++) {
                    mma8(acc[mt][nt], ahi[mt], bh0, bh1);
                    mma8(acc[mt][nt], alo[mt], bh0, bh1);
                    mma8(acc[mt][nt], ahi[mt], bl0, bl1);
                }
            }
        }

        // ReLU -> new recurrent state
        #pragma unroll
        for (int mt = 0; mt < 2; mt++)
            #pragma unroll
            for (int nt = 0; nt < 8; nt++)
                #pragma unroll
                for (int e = 0; e < 4; e++)
                    acc[mt][nt][e] = fmaxf(acc[mt][nt][e], 0.f);

        __syncthreads();   // all reads of h_{t-1} done
        #pragma unroll
        for (int mt = 0; mt < 2; mt++) {
            int rb = m0 + mt * 16 + g;
            #pragma unroll
            for (int nt = 0; nt < 8; nt++) {
                int j = n0 + nt * 8 + 2 * q;
                *(float2*)&hs[rb * HSS + j] = make_float2(acc[mt][nt][0], acc[mt][nt][1]);
                *(float2*)&hs[(rb + 8) * HSS + j] = make_float2(acc[mt][nt][2], acc[mt][nt][3]);
            }
        }
        __syncthreads();   // h_t visible

        // ---- scalar epilogue: LN + attn + dense from SMEM ----
        float e[8][8];
        #pragma unroll
        for (int i = 0; i < 8; i++) {
            float4 v0 = *(const float4*)&hs[(er0 + i) * HSS + ec0];
            float4 v1 = *(const float4*)&hs[(er0 + i) * HSS + ec0 + 4];
            e[i][0] = v0.x; e[i][1] = v0.y; e[i][2] = v0.z; e[i][3] = v0.w;
            e[i][4] = v1.x; e[i][5] = v1.y; e[i][6] = v1.z; e[i][7] = v1.w;
        }
        float mu[8], rs[8];
        #pragma unroll
        for (int i = 0; i < 8; i++) {
            float s = 0.f, qq = 0.f;
            #pragma unroll
            for (int c = 0; c < 8; c++) { s += e[i][c]; qq += e[i][c] * e[i][c]; }
            s = red16(s);
            qq = red16(qq);
            float m = s * (1.f / 128.f);
            float v = qq * (1.f / 128.f) - m * m;
            mu[i] = m;
            rs[i] = rsqrtf(v + LN_EPS);
        }
        #pragma unroll
        for (int i = 0; i < 8; i++)
            #pragma unroll
            for (int c = 0; c < 8; c++)
                e[i][c] = (e[i][c] - mu[i]) * rs[i] * gam[c] + bet[c];

        // attention logit
        #pragma unroll
        for (int i = 0; i < 8; i++) {
            float s = 0.f;
            #pragma unroll
            for (int c = 0; c < 8; c++) s = fmaf(e[i][c], aw[c], s);
            s = red16(s);
            if (tx == 0) g_L[(size_t)t * NB + row0 + er0 + i] = s + ab;
        }

        // dense head
        #pragma unroll
        for (int cls = 0; cls < CD; cls++) {
            float4 w0 = *(const float4*)&dWs[cls * HD + ec0];
            float4 w1 = *(const float4*)&dWs[cls * HD + ec0 + 4];
            float wb[8] = {w0.x, w0.y, w0.z, w0.w, w1.x, w1.y, w1.z, w1.w};
            #pragma unroll
            for (int i = 0; i < 8; i++) {
                float s = 0.f;
                #pragma unroll
                for (int c = 0; c < 8; c++) s = fmaf(e[i][c], wb[c], s);
                s = red16(s);
                if (tx == 0)
                    g_D[((size_t)t * NB + row0 + er0 + i) * CD + cls] = s + db[cls];
            }
        }
        // next iteration's first __syncthreads protects hs overwrite
    }
}

// ---------------------------------------------------------------------------
// Kernel 3: softmax over T + attention-weighted sum -> out (N, 10)
// ---------------------------------------------------------------------------
extern "C" __global__ void k3_attn(float* __restrict__ out)
{
    int n = blockIdx.x * 256 + threadIdx.x;
    if (n >= NB) return;

    float lw[T_STEPS];
    float m = -1e30f;
    #pragma unroll
    for (int t = 0; t < T_STEPS; t++) {
        lw[t] = g_L[(size_t)t * NB + n];
        m = fmaxf(m, lw[t]);
    }
    float s = 0.f;
    #pragma unroll
    for (int t = 0; t < T_STEPS; t++) {
        lw[t] = expf(lw[t] - m);
        s += lw[t];
    }
    float inv = 1.f / s;

    float acc[CD];
    #pragma unroll
    for (int c = 0; c < CD; c++) acc[c] = 0.f;
    for (int t = 0; t < T_STEPS; t++) {
        float w = lw[t] * inv;
        const float* dp = g_D + ((size_t)t * NB + n) * CD;
        #pragma unroll
        for (int c = 0; c < CD; c++) acc[c] = fmaf(w, dp[c], acc[c]);
    }
    #pragma unroll
    for (int c = 0; c < CD; c++) out[n * CD + c] = acc[c];
}

// ---------------------------------------------------------------------------
extern "C" void kernel_launch(void* const* d_in, const int* in_sizes, int n_in,
                              void* d_out, int out_size)
{
    const float* X       = (const float*)d_in[0];
    const float* W_ih    = (const float*)d_in[1];
    const float* W_hh    = (const float*)d_in[2];
    const float* b_ih    = (const float*)d_in[3];
    const float* b_hh    = (const float*)d_in[4];
    const float* ln_g    = (const float*)d_in[5];
    const float* ln_b    = (const float*)d_in[6];
    const float* attn_W  = (const float*)d_in[7];
    const float* attn_b  = (const float*)d_in[8];
    const float* dense_W = (const float*)d_in[9];
    const float* dense_b = (const float*)d_in[10];
    (void)in_sizes; (void)n_in; (void)out_size;

    const int smem1 = (2 * 128 * WS2 + 2 * K1_ROWS * XSS) * (int)sizeof(float);    // 208,896 B
    const int smem2 = (2 * 128 * WS2 + MR * HSS + CD * HD) * (int)sizeof(float);   // 224,768 B
    cudaFuncSetAttribute(k1_zgemm, cudaFuncAttributeMaxDynamicSharedMemorySize, smem1);
    cudaFuncSetAttribute(k2_recur, cudaFuncAttributeMaxDynamicSharedMemorySize, smem2);

    k1_zgemm<<<(T_STEPS * NB) / K1_ROWS, K1_THREADS, smem1>>>(X, W_ih, b_ih, b_hh);
    k2_recur<<<NB / MR, K2_THREADS, smem2>>>(W_hh, ln_g, ln_b,
                                             attn_W, attn_b, dense_W, dense_b);
    k3_attn<<<(NB + 255) / 256, 256>>>((float*)d_out);
}

// round 14
// speedup vs baseline: 1.4917x; 1.0683x over previous
#include <cuda_runtime.h>
#include <math.h>
#include <stdint.h>

#define T_STEPS 32
#define NB 20000
#define FD 128
#define HD 128
#define CD 10
#define LN_EPS 1e-5f

#define MR 160            // k2 rows per CTA: 125 CTAs exactly, single wave
#define K2_THREADS 320    // 10 warps: 5 m x 2 n (32x64 warp tiles)
#define K1_ROWS 256
#define K1_THREADS 512    // 16 warps: 8 m x 2 n

#define WS2 132           // W smem row stride in float2: >=128 cap, conflict-free B loads
#define HSS 132           // hs row stride (floats): 132%32==4 -> conflict-free A loads
#define XSS 36            // X chunk row stride (floats): 36%32==4

// Scratch (static __device__ — allocation-free per harness rules)
__device__ float g_Z[(size_t)T_STEPS * NB * HD];

__device__ __forceinline__ uint32_t f2tf32(float x) {
    uint32_t r;
    asm("cvt.rna.tf32.f32 %0, %1;" : "=r"(r) : "f"(x));
    return r;
}

// D += A * B, m16n8k8 tf32, acc in-place
__device__ __forceinline__ void mma8(float* c, const uint32_t* a, uint32_t b0, uint32_t b1) {
    asm volatile(
        "mma.sync.aligned.m16n8k8.row.col.f32.tf32.tf32.f32 "
        "{%0,%1,%2,%3}, {%4,%5,%6,%7}, {%8,%9}, {%0,%1,%2,%3};"
        : "+f"(c[0]), "+f"(c[1]), "+f"(c[2]), "+f"(c[3])
        : "r"(a[0]), "r"(a[1]), "r"(a[2]), "r"(a[3]), "r"(b0), "r"(b1));
}

// split fp32 -> (tf32 hi, tf32 lo) register pair
__device__ __forceinline__ void split_tf32(float x, uint32_t& hi, uint32_t& lo) {
    hi = f2tf32(x);
    lo = f2tf32(x - __uint_as_float(hi));
}

// ---------------------------------------------------------------------------
// Kernel 1: Z = X @ W_ih^T + (b_ih + b_hh), tensor cores (3xTF32).
// 2500 CTAs x 256 rows, 512 thr (16 warps: 8m x 2n of 32x64 tiles).
// ---------------------------------------------------------------------------
extern "C" __global__ void __launch_bounds__(K1_THREADS, 1)
k1_zgemm(const float* __restrict__ X, const float* __restrict__ W_ih,
         const float* __restrict__ b_ih, const float* __restrict__ b_hh)
{
    extern __shared__ float smraw[];
    float2* Wp  = (float2*)smraw;               // [128][WS2] (hi, lo) of W_ih^T
    float*  Xs0 = smraw + 2 * 128 * WS2;        // [256][XSS]
    float*  Xs1 = Xs0 + K1_ROWS * XSS;

    const int tid = threadIdx.x;
    for (int idx = tid; idx < HD * FD; idx += K1_THREADS) {
        int j = idx >> 7, k = idx & 127;
        float w = W_ih[idx];
        uint32_t hb, lb;
        split_tf32(w, hb, lb);
        Wp[k * WS2 + j] = make_float2(__uint_as_float(hb), __uint_as_float(lb));
    }

    const int row0 = blockIdx.x * K1_ROWS;
    const int wid  = tid >> 5, lane = tid & 31;
    const int g = lane >> 2, q = lane & 3;
    const int m0 = (wid & 7) * 32, n0 = (wid >> 3) * 64;

    const int lr = tid >> 3, lc = tid & 7;
    auto load_chunk = [&](float* dst, int kb) {
        #pragma unroll
        for (int p = 0; p < 4; p++) {
            int r = lr + p * 64;
            float4 v = *reinterpret_cast<const float4*>(
                X + (size_t)(row0 + r) * FD + kb * 32 + lc * 4);
            *reinterpret_cast<float4*>(dst + r * XSS + lc * 4) = v;
        }
    };

    float acc[2][8][4];
    #pragma unroll
    for (int nt = 0; nt < 8; nt++) {
        int j = n0 + nt * 8 + 2 * q;
        float bx = b_ih[j] + b_hh[j];
        float by = b_ih[j + 1] + b_hh[j + 1];
        #pragma unroll
        for (int mt = 0; mt < 2; mt++) {
            acc[mt][nt][0] = bx; acc[mt][nt][1] = by;
            acc[mt][nt][2] = bx; acc[mt][nt][3] = by;
        }
    }

    load_chunk(Xs0, 0);
    __syncthreads();

    #pragma unroll 1
    for (int kb = 0; kb < 4; kb++) {
        float* cur = (kb & 1) ? Xs1 : Xs0;
        float* nxt = (kb & 1) ? Xs0 : Xs1;
        if (kb < 3) load_chunk(nxt, kb + 1);

        #pragma unroll
        for (int k0 = 0; k0 < 32; k0 += 8) {
            uint32_t ahi[2][4], alo[2][4];
            #pragma unroll
            for (int mt = 0; mt < 2; mt++) {
                int rb = m0 + mt * 16 + g;
                split_tf32(cur[rb * XSS + k0 + q],           ahi[mt][0], alo[mt][0]);
                split_tf32(cur[(rb + 8) * XSS + k0 + q],     ahi[mt][1], alo[mt][1]);
                split_tf32(cur[rb * XSS + k0 + q + 4],       ahi[mt][2], alo[mt][2]);
                split_tf32(cur[(rb + 8) * XSS + k0 + q + 4], ahi[mt][3], alo[mt][3]);
            }
            #pragma unroll
            for (int nt = 0; nt < 8; nt++) {
                float2 w0 = Wp[(kb * 32 + k0 + q) * WS2 + n0 + nt * 8 + g];
                float2 w1 = Wp[(kb * 32 + k0 + q + 4) * WS2 + n0 + nt * 8 + g];
                uint32_t bh0 = __float_as_uint(w0.x), bh1 = __float_as_uint(w1.x);
                uint32_t bl0 = __float_as_uint(w0.y), bl1 = __float_as_uint(w1.y);
                #pragma unroll
                for (int mt = 0; mt < 2; mt++) {
                    mma8(acc[mt][nt], ahi[mt], bh0, bh1);
                    mma8(acc[mt][nt], alo[mt], bh0, bh1);
                    mma8(acc[mt][nt], ahi[mt], bl0, bl1);
                }
            }
        }
        __syncthreads();
    }

    #pragma unroll
    for (int mt = 0; mt < 2; mt++) {
        int r = row0 + m0 + mt * 16 + g;
        #pragma unroll
        for (int nt = 0; nt < 8; nt++) {
            int j = n0 + nt * 8 + 2 * q;
            *(float2*)&g_Z[(size_t)r * HD + j] =
                make_float2(acc[mt][nt][0], acc[mt][nt][1]);
            *(float2*)&g_Z[(size_t)(r + 8) * HD + j] =
                make_float2(acc[mt][nt][2], acc[mt][nt][3]);
        }
    }
}

// ---------------------------------------------------------------------------
__device__ __forceinline__ float red16(float v)
{
    v += __shfl_xor_sync(0xffffffffu, v, 1);
    v += __shfl_xor_sync(0xffffffffu, v, 2);
    v += __shfl_xor_sync(0xffffffffu, v, 4);
    v += __shfl_xor_sync(0xffffffffu, v, 8);
    return v;
}

// ---------------------------------------------------------------------------
// Kernel 2: recurrence + ONLINE softmax-attention accumulation.
// 125 CTAs x 160 rows. Per step: acc = Z[t]; acc += h@W_hh^T (3xTF32);
// relu -> hs; LN stats (3 red16/row) -> logit -> online-softmax update of
// hacc (LN'd h weighted). Dense head applied ONCE after the t-loop.
// Writes d_out directly; no g_L/g_D, no k3.
// ---------------------------------------------------------------------------
extern "C" __global__ void __launch_bounds__(K2_THREADS, 1)
k2_recur(float* __restrict__ out,
         const float* __restrict__ W_hh,
         const float* __restrict__ ln_gamma, const float* __restrict__ ln_beta,
         const float* __restrict__ attn_W,   const float* __restrict__ attn_b,
         const float* __restrict__ dense_W,  const float* __restrict__ dense_b)
{
    extern __shared__ float smraw[];
    float2* Wp  = (float2*)smraw;               // [128][WS2] (hi, lo) of W_hh^T
    float*  hs  = smraw + 2 * 128 * WS2;        // [160][HSS]
    float*  dWs = hs + MR * HSS;                // [10][128]

    const int tid = threadIdx.x;
    for (int idx = tid; idx < HD * HD; idx += K2_THREADS) {
        int j = idx >> 7, k = idx & 127;
        float w = W_hh[idx];
        uint32_t hb, lb;
        split_tf32(w, hb, lb);
        Wp[k * WS2 + j] = make_float2(__uint_as_float(hb), __uint_as_float(lb));
    }
    for (int idx = tid; idx < CD * HD; idx += K2_THREADS) dWs[idx] = dense_W[idx];

    const int row0 = blockIdx.x * MR;
    const int wid  = tid >> 5, lane = tid & 31;
    const int g = lane >> 2, q = lane & 3;
    const int m0 = (wid >> 1) * 32, n0 = (wid & 1) * 64;

    // epilogue mapping: 20 ty x 16 tx, 8 rows x 8 cols per thread
    const int ty = tid / 16, tx = tid % 16;
    const int er0 = ty * 8, ec0 = tx * 8;

    float gam[8], bet[8], gaw[8];
    float pg = 0.f, pb = 0.f;
    #pragma unroll
    for (int c = 0; c < 8; c++) {
        gam[c] = ln_gamma[ec0 + c];
        bet[c] = ln_beta[ec0 + c];
        float a = attn_W[ec0 + c];
        gaw[c] = gam[c] * a;
        pg += gaw[c];
        pb += bet[c] * a;
    }
    const float Gaw = red16(pg);                 // sum(gamma*aw) over 128
    const float Bc  = red16(pb) + attn_b[0];     // sum(beta*aw) + attn bias

    // online-softmax state (per row) + weighted LN'd-h accumulator
    float m_run[8], s_run[8], hacc[8][8];
    #pragma unroll
    for (int i = 0; i < 8; i++) {
        m_run[i] = -1e30f;
        s_run[i] = 0.f;
        #pragma unroll
        for (int c = 0; c < 8; c++) hacc[i][c] = 0.f;
    }

    // h0 = Z[0] (reference init branch: no ReLU)
    for (int f = tid; f < MR * 32; f += K2_THREADS) {
        int r = f >> 5, c4 = (f & 31) * 4;
        float4 v = *(const float4*)&g_Z[(size_t)(row0 + r) * HD + c4];
        *(float4*)&hs[r * HSS + c4] = v;
    }
    __syncthreads();

    #pragma unroll 1
    for (int t = 0; t < T_STEPS; t++) {
        const float* Zt = g_Z + ((size_t)t * NB + row0) * HD;

        // acc init = Z[t] in fragment layout
        float acc[2][8][4];
        #pragma unroll
        for (int mt = 0; mt < 2; mt++) {
            int rb = m0 + mt * 16 + g;
            #pragma unroll
            for (int nt = 0; nt < 8; nt++) {
                int j = n0 + nt * 8 + 2 * q;
                float2 z0 = *(const float2*)&Zt[(size_t)rb * HD + j];
                float2 z1 = *(const float2*)&Zt[(size_t)(rb + 8) * HD + j];
                acc[mt][nt][0] = z0.x; acc[mt][nt][1] = z0.y;
                acc[mt][nt][2] = z1.x; acc[mt][nt][3] = z1.y;
            }
        }

        // acc += h @ W_hh^T (3xTF32)
        #pragma unroll 2
        for (int k0 = 0; k0 < HD; k0 += 8) {
            uint32_t ahi[2][4], alo[2][4];
            #pragma unroll
            for (int mt = 0; mt < 2; mt++) {
                int rb = m0 + mt * 16 + g;
                split_tf32(hs[rb * HSS + k0 + q],           ahi[mt][0], alo[mt][0]);
                split_tf32(hs[(rb + 8) * HSS + k0 + q],     ahi[mt][1], alo[mt][1]);
                split_tf32(hs[rb * HSS + k0 + q + 4],       ahi[mt][2], alo[mt][2]);
                split_tf32(hs[(rb + 8) * HSS + k0 + q + 4], ahi[mt][3], alo[mt][3]);
            }
            #pragma unroll
            for (int nt = 0; nt < 8; nt++) {
                float2 w0 = Wp[(k0 + q) * WS2 + n0 + nt * 8 + g];
                float2 w1 = Wp[(k0 + q + 4) * WS2 + n0 + nt * 8 + g];
                uint32_t bh0 = __float_as_uint(w0.x), bh1 = __float_as_uint(w1.x);
                uint32_t bl0 = __float_as_uint(w0.y), bl1 = __float_as_uint(w1.y);
                #pragma unroll
                for (int mt = 0; mt < 2; mt++) {
                    mma8(acc[mt][nt], ahi[mt], bh0, bh1);
                    mma8(acc[mt][nt], alo[mt], bh0, bh1);
                    mma8(acc[mt][nt], ahi[mt], bl0, bl1);
                }
            }
        }

        // ReLU -> new recurrent state
        #pragma unroll
        for (int mt = 0; mt < 2; mt++)
            #pragma unroll
            for (int nt = 0; nt < 8; nt++)
                #pragma unroll
                for (int e = 0; e < 4; e++)
                    acc[mt][nt][e] = fmaxf(acc[mt][nt][e], 0.f);

        __syncthreads();   // all reads of h_{t-1} done
        #pragma unroll
        for (int mt = 0; mt < 2; mt++) {
            int rb = m0 + mt * 16 + g;
            #pragma unroll
            for (int nt = 0; nt < 8; nt++) {
                int j = n0 + nt * 8 + 2 * q;
                *(float2*)&hs[rb * HSS + j] = make_float2(acc[mt][nt][0], acc[mt][nt][1]);
                *(float2*)&hs[(rb + 8) * HSS + j] = make_float2(acc[mt][nt][2], acc[mt][nt][3]);
            }
        }
        __syncthreads();   // h_t visible

        // ---- epilogue: LN stats + logit + online softmax accumulation ----
        #pragma unroll
        for (int i = 0; i < 8; i++) {
            float e8[8];
            {
                float4 v0 = *(const float4*)&hs[(er0 + i) * HSS + ec0];
                float4 v1 = *(const float4*)&hs[(er0 + i) * HSS + ec0 + 4];
                e8[0] = v0.x; e8[1] = v0.y; e8[2] = v0.z; e8[3] = v0.w;
                e8[4] = v1.x; e8[5] = v1.y; e8[6] = v1.z; e8[7] = v1.w;
            }
            float sv = 0.f, qv = 0.f, hg = 0.f;
            #pragma unroll
            for (int c = 0; c < 8; c++) {
                sv += e8[c];
                qv = fmaf(e8[c], e8[c], qv);
                hg = fmaf(e8[c], gaw[c], hg);
            }
            sv = red16(sv);
            qv = red16(qv);
            hg = red16(hg);
            float muv = sv * (1.f / 128.f);
            float var = qv * (1.f / 128.f) - muv * muv;
            float rsv = rsqrtf(var + LN_EPS);
            float logit = rsv * (hg - muv * Gaw) + Bc;

            float mo = m_run[i];
            float mn = fmaxf(mo, logit);
            float sc = __expf(mo - mn);
            float p  = __expf(logit - mn);
            s_run[i] = s_run[i] * sc + p;
            m_run[i] = mn;
            #pragma unroll
            for (int c = 0; c < 8; c++) {
                float en = fmaf((e8[c] - muv) * rsv, gam[c], bet[c]);
                hacc[i][c] = fmaf(hacc[i][c], sc, p * en);
            }
        }
        // next iteration's first __syncthreads protects hs overwrite
    }

    // ---- final: dense head on attention-weighted LN'd state ----
    #pragma unroll
    for (int i = 0; i < 8; i++) {
        float inv = 1.f / s_run[i];
        #pragma unroll
        for (int cls = 0; cls < CD; cls++) {
            const float* wr = dWs + cls * HD + ec0;
            float pp = 0.f;
            #pragma unroll
            for (int c = 0; c < 8; c++) pp = fmaf(hacc[i][c], wr[c], pp);
            pp = red16(pp);
            if (tx == 0)
                out[(size_t)(row0 + er0 + i) * CD + cls] = pp * inv + dense_b[cls];
        }
    }
}

// ---------------------------------------------------------------------------
extern "C" void kernel_launch(void* const* d_in, const int* in_sizes, int n_in,
                              void* d_out, int out_size)
{
    const float* X       = (const float*)d_in[0];
    const float* W_ih    = (const float*)d_in[1];
    const float* W_hh    = (const float*)d_in[2];
    const float* b_ih    = (const float*)d_in[3];
    const float* b_hh    = (const float*)d_in[4];
    const float* ln_g    = (const float*)d_in[5];
    const float* ln_b    = (const float*)d_in[6];
    const float* attn_W  = (const float*)d_in[7];
    const float* attn_b  = (const float*)d_in[8];
    const float* dense_W = (const float*)d_in[9];
    const float* dense_b = (const float*)d_in[10];
    (void)in_sizes; (void)n_in; (void)out_size;

    const int smem1 = (2 * 128 * WS2 + 2 * K1_ROWS * XSS) * (int)sizeof(float);
    const int smem2 = (2 * 128 * WS2 + MR * HSS + CD * HD) * (int)sizeof(float);
    cudaFuncSetAttribute(k1_zgemm, cudaFuncAttributeMaxDynamicSharedMemorySize, smem1);
    cudaFuncSetAttribute(k2_recur, cudaFuncAttributeMaxDynamicSharedMemorySize, smem2);

    k1_zgemm<<<(T_STEPS * NB) / K1_ROWS, K1_THREADS, smem1>>>(X, W_ih, b_ih, b_hh);
    k2_recur<<<NB / MR, K2_THREADS, smem2>>>((float*)d_out, W_hh, ln_g, ln_b,
                                             attn_W, attn_b, dense_W, dense_b);
}